// round 3
// baseline (speedup 1.0000x reference)
#include <cuda_runtime.h>
#include <cuda_fp16.h>
#include <cstdint>
#include <cstddef>

#define CDIM 768
#define NTOK 32768            // B*N = 8*4096
#define HDIM 96

// ---------------- GEMM tiling ----------------
#define BM 128
#define BN 128
#define BK 64                 // 64 fp16 = 128B rows -> SW128 swizzle, conflict-free ldmatrix
#define NKC (CDIM / BK)       // 12
#define A_STAGE_BYTES (BM * BK * 2)          // 16384
#define B_STAGE_BYTES (BN * BK * 2)          // 16384
#define STAGE_BYTES (A_STAGE_BYTES + B_STAGE_BYTES)   // 32768
#define SMEM_BYTES (2 * STAGE_BYTES)                   // 65536

// ---------------- scratch (device globals; no allocation allowed) ----------------
__device__ __align__(16) __half g_q[(size_t)NTOK * CDIM];
__device__ __align__(16) __half g_k[(size_t)2 * NTOK * CDIM];
__device__ __align__(16) __half g_v[(size_t)2 * NTOK * CDIM];
__device__ __align__(16) __half g_x[(size_t)NTOK * CDIM];
__device__ __align__(16) __half g_wq[CDIM * CDIM];
__device__ __align__(16) __half g_wk[CDIM * CDIM];
__device__ __align__(16) __half g_wp[CDIM * CDIM];

// ---------------- helpers ----------------
__device__ __forceinline__ uint32_t smem_u32(const void* p) {
    uint32_t a;
    asm("{ .reg .u64 t; cvta.to.shared.u64 t, %1; cvt.u32.u64 %0, t; }" : "=r"(a) : "l"(p));
    return a;
}

__device__ __forceinline__ void cp16(uint32_t dst, const void* src) {
    asm volatile("cp.async.cg.shared.global [%0], [%1], 16;" :: "r"(dst), "l"(src));
}
#define CP_COMMIT() asm volatile("cp.async.commit_group;" ::: "memory")
#define CP_WAIT0()  asm volatile("cp.async.wait_group 0;" ::: "memory")

__device__ __forceinline__ void ldm_x4(uint32_t (&r)[4], uint32_t addr) {
    asm volatile("ldmatrix.sync.aligned.m8n8.x4.shared.b16 {%0,%1,%2,%3}, [%4];"
                 : "=r"(r[0]), "=r"(r[1]), "=r"(r[2]), "=r"(r[3]) : "r"(addr));
}

__device__ __forceinline__ void mma16816(float (&c)[4], const uint32_t (&a)[4],
                                         uint32_t b0, uint32_t b1) {
    asm volatile(
        "mma.sync.aligned.m16n8k16.row.col.f32.f16.f16.f32 "
        "{%0,%1,%2,%3}, {%4,%5,%6,%7}, {%8,%9}, {%0,%1,%2,%3};"
        : "+f"(c[0]), "+f"(c[1]), "+f"(c[2]), "+f"(c[3])
        : "r"(a[0]), "r"(a[1]), "r"(a[2]), "r"(a[3]), "r"(b0), "r"(b1));
}

__device__ __forceinline__ uint32_t pack_h2(float a, float b) {
    __half2 h = __floats2half2_rn(a, b);
    return *reinterpret_cast<uint32_t*>(&h);
}

// ---------------- weight fp32 -> fp16 ----------------
__global__ void convert_w_kernel(const float* __restrict__ wq,
                                 const float* __restrict__ wk,
                                 const float* __restrict__ wp) {
    const int n4 = CDIM * CDIM / 4;
    int idx = blockIdx.x * blockDim.x + threadIdx.x;
    if (idx >= 3 * n4) return;
    int w = idx / n4;
    int j = idx - w * n4;
    const float* src = (w == 0) ? wq : (w == 1) ? wk : wp;
    __half* dst = (w == 0) ? g_wq : (w == 1) ? g_wk : g_wp;
    float4 f = reinterpret_cast<const float4*>(src)[j];
    uint2 u;
    u.x = pack_h2(f.x, f.y);
    u.y = pack_h2(f.z, f.w);
    reinterpret_cast<uint2*>(dst)[j] = u;
}

// ---------------- HMMA GEMM: D[M,768] = A[M,768] @ W^T (+bias) ----------------
// Layout per stage: A tile [BM][BK] fp16 at +0, B tile [BN][BK] fp16 at +16384.
// SW128 swizzle: element (row, 16B-slot s) stored at row*128 + ((s ^ (row&7))<<4).
template <bool A_HALF, bool FINAL>
__global__ void __launch_bounds__(256, 1)
gemm_kernel(const void* __restrict__ Aptr, const __half* __restrict__ Wh,
            const float* __restrict__ bias, void* __restrict__ Dptr) {
    extern __shared__ char smem[];
    const uint32_t sb = smem_u32(smem);
    const int tid = threadIdx.x;
    const int wid = tid >> 5;
    const int lane = tid & 31;
    const int m0 = blockIdx.x * BM;
    const int n0 = blockIdx.y * BN;
    const int wm = wid >> 2;          // 0..1 : 64 rows each
    const int wn = wid & 3;           // 0..3 : 32 cols each

    float acc[4][4][4];
    #pragma unroll
    for (int i = 0; i < 4; i++)
        #pragma unroll
        for (int j = 0; j < 4; j++)
            #pragma unroll
            for (int l = 0; l < 4; l++) acc[i][j][l] = 0.f;

    float4 areg[8];                   // fp32-A staging (only used when !A_HALF)

    // ---- prologue: stage 0 <- chunk 0 ----
    {
        const uint32_t st = 0;
        if (A_HALF) {
            const __half* A = (const __half*)Aptr + (size_t)m0 * CDIM;
            #pragma unroll
            for (int j = 0; j < 4; j++) {
                int idx = tid + j * 256;            // 1024 chunks of 16B
                int r = idx >> 3, s = idx & 7;
                cp16(sb + st + r * 128 + (((uint32_t)(s ^ (r & 7))) << 4),
                     A + (size_t)r * CDIM + s * 8);
            }
        } else {
            const float* A = (const float*)Aptr + (size_t)m0 * CDIM;
            #pragma unroll
            for (int j = 0; j < 8; j++) {
                int idx = tid + j * 256;            // 2048 float4 groups
                int r = idx >> 4, g = idx & 15;
                float4 f = *reinterpret_cast<const float4*>(A + (size_t)r * CDIM + g * 4);
                int s = g >> 1;
                uint32_t off = st + r * 128 + (((uint32_t)(s ^ (r & 7))) << 4) + (g & 1) * 8;
                uint2 u;
                u.x = pack_h2(f.x, f.y);
                u.y = pack_h2(f.z, f.w);
                *reinterpret_cast<uint2*>(smem + off) = u;
            }
        }
        const __half* W = Wh + (size_t)n0 * CDIM;
        #pragma unroll
        for (int j = 0; j < 4; j++) {
            int idx = tid + j * 256;
            int r = idx >> 3, s = idx & 7;
            cp16(sb + st + A_STAGE_BYTES + r * 128 + (((uint32_t)(s ^ (r & 7))) << 4),
                 W + (size_t)r * CDIM + s * 8);
        }
        CP_COMMIT();
        CP_WAIT0();
        __syncthreads();
    }

    for (int kc = 0; kc < NKC; kc++) {
        const int cur = kc & 1;
        const int nxt = cur ^ 1;
        const bool more = (kc + 1 < NKC);
        const uint32_t stc = cur * STAGE_BYTES;
        const uint32_t stn = nxt * STAGE_BYTES;

        // ---- issue next-chunk loads (overlap with compute) ----
        if (more) {
            if (A_HALF) {
                const __half* A = (const __half*)Aptr + (size_t)m0 * CDIM + (kc + 1) * BK;
                #pragma unroll
                for (int j = 0; j < 4; j++) {
                    int idx = tid + j * 256;
                    int r = idx >> 3, s = idx & 7;
                    cp16(sb + stn + r * 128 + (((uint32_t)(s ^ (r & 7))) << 4),
                         A + (size_t)r * CDIM + s * 8);
                }
            } else {
                const float* A = (const float*)Aptr + (size_t)m0 * CDIM + (kc + 1) * BK;
                #pragma unroll
                for (int j = 0; j < 8; j++) {
                    int idx = tid + j * 256;
                    int r = idx >> 4, g = idx & 15;
                    areg[j] = *reinterpret_cast<const float4*>(A + (size_t)r * CDIM + g * 4);
                }
            }
            const __half* W = Wh + (size_t)n0 * CDIM + (kc + 1) * BK;
            #pragma unroll
            for (int j = 0; j < 4; j++) {
                int idx = tid + j * 256;
                int r = idx >> 3, s = idx & 7;
                cp16(sb + stn + A_STAGE_BYTES + r * 128 + (((uint32_t)(s ^ (r & 7))) << 4),
                     W + (size_t)r * CDIM + s * 8);
            }
            CP_COMMIT();
        }

        // ---- compute on current stage ----
        const uint32_t Ab = sb + stc;
        const uint32_t Bb = sb + stc + A_STAGE_BYTES;
        #pragma unroll
        for (int ks = 0; ks < 4; ks++) {
            uint32_t afrag[4][4];
            #pragma unroll
            for (int im = 0; im < 4; im++) {
                int row = wm * 64 + im * 16 + (lane & 15);
                int slot = ks * 2 + (lane >> 4);
                ldm_x4(afrag[im], Ab + row * 128 + (((uint32_t)(slot ^ (row & 7))) << 4));
            }
            uint32_t bfrag[2][4];
            #pragma unroll
            for (int jn = 0; jn < 2; jn++) {
                int grp = lane >> 3;
                int nrow = wn * 32 + jn * 16 + (grp >> 1) * 8 + (lane & 7);
                int slot = ks * 2 + (grp & 1);
                ldm_x4(bfrag[jn], Bb + nrow * 128 + (((uint32_t)(slot ^ (nrow & 7))) << 4));
            }
            #pragma unroll
            for (int im = 0; im < 4; im++)
                #pragma unroll
                for (int in = 0; in < 4; in++)
                    mma16816(acc[im][in], afrag[im],
                             bfrag[in >> 1][(in & 1) * 2 + 0],
                             bfrag[in >> 1][(in & 1) * 2 + 1]);
        }

        // ---- finish next-stage fill ----
        if (more) {
            CP_WAIT0();
            if (!A_HALF) {
                #pragma unroll
                for (int j = 0; j < 8; j++) {
                    int idx = tid + j * 256;
                    int r = idx >> 4, g = idx & 15;
                    int s = g >> 1;
                    uint32_t off = stn + r * 128 + (((uint32_t)(s ^ (r & 7))) << 4) + (g & 1) * 8;
                    uint2 u;
                    u.x = pack_h2(areg[j].x, areg[j].y);
                    u.y = pack_h2(areg[j].z, areg[j].w);
                    *reinterpret_cast<uint2*>(smem + off) = u;
                }
            }
        }
        __syncthreads();
    }

    // ---- epilogue ----
    #pragma unroll
    for (int im = 0; im < 4; im++) {
        int r0 = m0 + wm * 64 + im * 16 + (lane >> 2);
        #pragma unroll
        for (int in = 0; in < 4; in++) {
            int col = n0 + wn * 32 + in * 8 + (lane & 3) * 2;
            if (FINAL) {
                float* D = (float*)Dptr;
                float b0 = bias[col], b1 = bias[col + 1];
                float2 v0 = make_float2(acc[im][in][0] + b0, acc[im][in][1] + b1);
                float2 v1 = make_float2(acc[im][in][2] + b0, acc[im][in][3] + b1);
                *reinterpret_cast<float2*>(D + (size_t)r0 * CDIM + col) = v0;
                *reinterpret_cast<float2*>(D + (size_t)(r0 + 8) * CDIM + col) = v1;
            } else {
                __half* D = (__half*)Dptr;
                *reinterpret_cast<uint32_t*>(D + (size_t)r0 * CDIM + col) =
                    pack_h2(acc[im][in][0], acc[im][in][1]);
                *reinterpret_cast<uint32_t*>(D + (size_t)(r0 + 8) * CDIM + col) =
                    pack_h2(acc[im][in][2], acc[im][in][3]);
            }
        }
    }
}

// ---------------- per-token 2-way attention ----------------
__global__ void __launch_bounds__(256) attn_kernel() {
    int gid = blockIdx.x * blockDim.x + threadIdx.x;   // 262144 = 32768 tokens * 8 heads
    int t = gid >> 3;
    int h = gid & 7;

    const __half* q  = g_q + (size_t)t * CDIM + h * HDIM;
    const __half* k0 = g_k + (size_t)(2 * t) * CDIM + h * HDIM;
    const __half* k1 = k0 + CDIM;
    const __half* v0 = g_v + (size_t)(2 * t) * CDIM + h * HDIM;
    const __half* v1 = v0 + CDIM;

    float l0 = 0.f, l1 = 0.f;
    #pragma unroll
    for (int i = 0; i < 12; i++) {                     // 12 * 8 halves = 96
        int4 qa = *reinterpret_cast<const int4*>(q + i * 8);
        int4 ka = *reinterpret_cast<const int4*>(k0 + i * 8);
        int4 kb = *reinterpret_cast<const int4*>(k1 + i * 8);
        const __half2* qh = reinterpret_cast<const __half2*>(&qa);
        const __half2* k0h = reinterpret_cast<const __half2*>(&ka);
        const __half2* k1h = reinterpret_cast<const __half2*>(&kb);
        #pragma unroll
        for (int j = 0; j < 4; j++) {
            float2 qf = __half22float2(qh[j]);
            float2 a = __half22float2(k0h[j]);
            float2 b = __half22float2(k1h[j]);
            l0 = fmaf(qf.x, a.x, l0); l0 = fmaf(qf.y, a.y, l0);
            l1 = fmaf(qf.x, b.x, l1); l1 = fmaf(qf.y, b.y, l1);
        }
    }
    const float scale = 0.1020620726159658f;           // 96^-0.5
    l0 *= scale; l1 *= scale;
    float m = fmaxf(l0, l1);
    float e0 = __expf(l0 - m), e1 = __expf(l1 - m);
    float inv = 1.f / (e0 + e1);
    float a0 = e0 * inv, a1 = e1 * inv;

    __half* x = g_x + (size_t)t * CDIM + h * HDIM;
    #pragma unroll
    for (int i = 0; i < 12; i++) {
        int4 va = *reinterpret_cast<const int4*>(v0 + i * 8);
        int4 vb = *reinterpret_cast<const int4*>(v1 + i * 8);
        const __half2* ah = reinterpret_cast<const __half2*>(&va);
        const __half2* bh = reinterpret_cast<const __half2*>(&vb);
        uint4 out;
        uint32_t* op = reinterpret_cast<uint32_t*>(&out);
        #pragma unroll
        for (int j = 0; j < 4; j++) {
            float2 fa = __half22float2(ah[j]);
            float2 fb = __half22float2(bh[j]);
            op[j] = pack_h2(a0 * fa.x + a1 * fb.x, a0 * fa.y + a1 * fb.y);
        }
        *reinterpret_cast<uint4*>(x + i * 8) = out;
    }
}

// ---------------- launch ----------------
extern "C" void kernel_launch(void* const* d_in, const int* in_sizes, int n_in,
                              void* d_out, int out_size) {
    const float* query = (const float*)d_in[0];
    const float* key   = (const float*)d_in[1];
    const float* value = (const float*)d_in[2];
    const float* Wq    = (const float*)d_in[3];
    const float* Wk    = (const float*)d_in[4];
    const float* Wp    = (const float*)d_in[5];
    const float* bp    = (const float*)d_in[6];

    cudaFuncSetAttribute(gemm_kernel<false, false>,
                         cudaFuncAttributeMaxDynamicSharedMemorySize, SMEM_BYTES);
    cudaFuncSetAttribute(gemm_kernel<true, true>,
                         cudaFuncAttributeMaxDynamicSharedMemorySize, SMEM_BYTES);

    __half *q, *k, *v, *x, *wq, *wk, *wp;
    cudaGetSymbolAddress((void**)&q,  g_q);
    cudaGetSymbolAddress((void**)&k,  g_k);
    cudaGetSymbolAddress((void**)&v,  g_v);
    cudaGetSymbolAddress((void**)&x,  g_x);
    cudaGetSymbolAddress((void**)&wq, g_wq);
    cudaGetSymbolAddress((void**)&wk, g_wk);
    cudaGetSymbolAddress((void**)&wp, g_wp);

    // 1) weights -> fp16
    convert_w_kernel<<<(3 * (CDIM * CDIM / 4) + 255) / 256, 256>>>(Wq, Wk, Wp);

    // 2-4) projections (note: reference applies Wk to BOTH key and value)
    gemm_kernel<false, false><<<dim3(NTOK / BM, CDIM / BN), 256, SMEM_BYTES>>>(query, wq, nullptr, q);
    gemm_kernel<false, false><<<dim3(2 * NTOK / BM, CDIM / BN), 256, SMEM_BYTES>>>(key, wk, nullptr, k);
    gemm_kernel<false, false><<<dim3(2 * NTOK / BM, CDIM / BN), 256, SMEM_BYTES>>>(value, wk, nullptr, v);

    // 5) per-token 2-way softmax attention
    attn_kernel<<<(NTOK * 8) / 256, 256>>>();

    // 6) output projection + bias (fp32 out)
    gemm_kernel<true, true><<<dim3(NTOK / BM, CDIM / BN), 256, SMEM_BYTES>>>(x, wp, bp, (float*)d_out);
}

// round 4
// speedup vs baseline: 1.0614x; 1.0614x over previous
#include <cuda_runtime.h>
#include <cuda_fp16.h>
#include <cstdint>
#include <cstddef>

#define CDIM 768
#define NTOK 32768            // B*N = 8*4096
#define HDIM 96

// ---------------- GEMM tiling ----------------
#define BM 128
#define BN 128
#define BK 64                 // 64 fp16 = 128B rows -> SW128 swizzle, conflict-free ldmatrix
#define NKC (CDIM / BK)       // 12
#define A_STAGE_BYTES (BM * BK * 2)          // 16384
#define B_STAGE_BYTES (BN * BK * 2)          // 16384
#define STAGE_BYTES (A_STAGE_BYTES + B_STAGE_BYTES)   // 32768
#define SMEM_BYTES (2 * STAGE_BYTES)                   // 65536

// ---------------- scratch (device globals; no allocation allowed) ----------------
__device__ __align__(16) __half g_q[(size_t)NTOK * CDIM];
__device__ __align__(16) __half g_k[(size_t)2 * NTOK * CDIM];
__device__ __align__(16) __half g_v[(size_t)2 * NTOK * CDIM];
__device__ __align__(16) __half g_x[(size_t)NTOK * CDIM];
__device__ __align__(16) __half g_wq[CDIM * CDIM];
__device__ __align__(16) __half g_wk[CDIM * CDIM];
__device__ __align__(16) __half g_wp[CDIM * CDIM];

// ---------------- helpers ----------------
__device__ __forceinline__ uint32_t smem_u32(const void* p) {
    uint32_t a;
    asm("{ .reg .u64 t; cvta.to.shared.u64 t, %1; cvt.u32.u64 %0, t; }" : "=r"(a) : "l"(p));
    return a;
}

__device__ __forceinline__ void cp16(uint32_t dst, const void* src) {
    asm volatile("cp.async.cg.shared.global [%0], [%1], 16;" :: "r"(dst), "l"(src));
}
#define CP_COMMIT() asm volatile("cp.async.commit_group;" ::: "memory")
#define CP_WAIT0()  asm volatile("cp.async.wait_group 0;" ::: "memory")

__device__ __forceinline__ void ldm_x4(uint32_t (&r)[4], uint32_t addr) {
    asm volatile("ldmatrix.sync.aligned.m8n8.x4.shared.b16 {%0,%1,%2,%3}, [%4];"
                 : "=r"(r[0]), "=r"(r[1]), "=r"(r[2]), "=r"(r[3]) : "r"(addr));
}

__device__ __forceinline__ void mma16816(float (&c)[4], const uint32_t (&a)[4],
                                         uint32_t b0, uint32_t b1) {
    asm volatile(
        "mma.sync.aligned.m16n8k16.row.col.f32.f16.f16.f32 "
        "{%0,%1,%2,%3}, {%4,%5,%6,%7}, {%8,%9}, {%0,%1,%2,%3};"
        : "+f"(c[0]), "+f"(c[1]), "+f"(c[2]), "+f"(c[3])
        : "r"(a[0]), "r"(a[1]), "r"(a[2]), "r"(a[3]), "r"(b0), "r"(b1));
}

__device__ __forceinline__ uint32_t pack_h2(float a, float b) {
    __half2 h = __floats2half2_rn(a, b);
    return *reinterpret_cast<uint32_t*>(&h);
}

// ---------------- weight fp32 -> fp16 ----------------
__global__ void convert_w_kernel(const float* __restrict__ wq,
                                 const float* __restrict__ wk,
                                 const float* __restrict__ wp) {
    const int n4 = CDIM * CDIM / 4;
    int idx = blockIdx.x * blockDim.x + threadIdx.x;
    if (idx >= 3 * n4) return;
    int w = idx / n4;
    int j = idx - w * n4;
    const float* src = (w == 0) ? wq : (w == 1) ? wk : wp;
    __half* dst = (w == 0) ? g_wq : (w == 1) ? g_wk : g_wp;
    float4 f = reinterpret_cast<const float4*>(src)[j];
    uint2 u;
    u.x = pack_h2(f.x, f.y);
    u.y = pack_h2(f.z, f.w);
    reinterpret_cast<uint2*>(dst)[j] = u;
}

// ---------------- HMMA GEMM: D[M,768] = A[M,768] @ W^T (+bias) ----------------
// Grid: (n-tiles, m-tiles) so CTAs sharing the same A panel are co-resident -> L2 reuse.
// Layout per stage: A tile [BM][BK] fp16 at +0, B tile [BN][BK] fp16 at +16384.
// SW128 swizzle: element (row, 16B-slot s) stored at row*128 + ((s ^ (row&7))<<4).
template <bool A_HALF, bool FINAL>
__global__ void __launch_bounds__(256, 1)
gemm_kernel(const void* __restrict__ Aptr, const __half* __restrict__ Wh,
            const float* __restrict__ bias, void* __restrict__ Dptr) {
    extern __shared__ char smem[];
    const uint32_t sb = smem_u32(smem);
    const int tid = threadIdx.x;
    const int wid = tid >> 5;
    const int lane = tid & 31;
    const int n0 = blockIdx.x * BN;   // n fastest -> A panel shared across co-resident CTAs
    const int m0 = blockIdx.y * BM;
    const int wm = wid >> 2;          // 0..1 : 64 rows each
    const int wn = wid & 3;           // 0..3 : 32 cols each

    float acc[4][4][4];
    #pragma unroll
    for (int i = 0; i < 4; i++)
        #pragma unroll
        for (int j = 0; j < 4; j++)
            #pragma unroll
            for (int l = 0; l < 4; l++) acc[i][j][l] = 0.f;

    float4 areg[8];                   // fp32-A staging (only used when !A_HALF)

    // ---- prologue: stage 0 <- chunk 0 ----
    {
        const uint32_t st = 0;
        if (A_HALF) {
            const __half* A = (const __half*)Aptr + (size_t)m0 * CDIM;
            #pragma unroll
            for (int j = 0; j < 4; j++) {
                int idx = tid + j * 256;            // 1024 chunks of 16B
                int r = idx >> 3, s = idx & 7;
                cp16(sb + st + r * 128 + (((uint32_t)(s ^ (r & 7))) << 4),
                     A + (size_t)r * CDIM + s * 8);
            }
        } else {
            const float* A = (const float*)Aptr + (size_t)m0 * CDIM;
            #pragma unroll
            for (int j = 0; j < 8; j++) {
                int idx = tid + j * 256;            // 2048 float4 groups
                int r = idx >> 4, g = idx & 15;
                float4 f = *reinterpret_cast<const float4*>(A + (size_t)r * CDIM + g * 4);
                int s = g >> 1;
                uint32_t off = st + r * 128 + (((uint32_t)(s ^ (r & 7))) << 4) + (g & 1) * 8;
                uint2 u;
                u.x = pack_h2(f.x, f.y);
                u.y = pack_h2(f.z, f.w);
                *reinterpret_cast<uint2*>(smem + off) = u;
            }
        }
        const __half* W = Wh + (size_t)n0 * CDIM;
        #pragma unroll
        for (int j = 0; j < 4; j++) {
            int idx = tid + j * 256;
            int r = idx >> 3, s = idx & 7;
            cp16(sb + st + A_STAGE_BYTES + r * 128 + (((uint32_t)(s ^ (r & 7))) << 4),
                 W + (size_t)r * CDIM + s * 8);
        }
        CP_COMMIT();
        CP_WAIT0();
        __syncthreads();
    }

    uint32_t afrag[2][4][4];
    uint32_t bfrag[2][2][4];

    for (int kc = 0; kc < NKC; kc++) {
        const int cur = kc & 1;
        const int nxt = cur ^ 1;
        const bool more = (kc + 1 < NKC);
        const uint32_t stc = cur * STAGE_BYTES;
        const uint32_t stn = nxt * STAGE_BYTES;

        // ---- issue next-chunk loads (overlap with compute) ----
        if (more) {
            if (A_HALF) {
                const __half* A = (const __half*)Aptr + (size_t)m0 * CDIM + (kc + 1) * BK;
                #pragma unroll
                for (int j = 0; j < 4; j++) {
                    int idx = tid + j * 256;
                    int r = idx >> 3, s = idx & 7;
                    cp16(sb + stn + r * 128 + (((uint32_t)(s ^ (r & 7))) << 4),
                         A + (size_t)r * CDIM + s * 8);
                }
            } else {
                const float* A = (const float*)Aptr + (size_t)m0 * CDIM + (kc + 1) * BK;
                #pragma unroll
                for (int j = 0; j < 8; j++) {
                    int idx = tid + j * 256;
                    int r = idx >> 4, g = idx & 15;
                    areg[j] = *reinterpret_cast<const float4*>(A + (size_t)r * CDIM + g * 4);
                }
            }
            const __half* W = Wh + (size_t)n0 * CDIM + (kc + 1) * BK;
            #pragma unroll
            for (int j = 0; j < 4; j++) {
                int idx = tid + j * 256;
                int r = idx >> 3, s = idx & 7;
                cp16(sb + stn + A_STAGE_BYTES + r * 128 + (((uint32_t)(s ^ (r & 7))) << 4),
                     W + (size_t)r * CDIM + s * 8);
            }
            CP_COMMIT();
        }

        // ---- compute on current stage (fragment double-buffered over ks) ----
        const uint32_t Ab = sb + stc;
        const uint32_t Bb = sb + stc + A_STAGE_BYTES;

        // preload ks = 0 into buffer 0
        #pragma unroll
        for (int im = 0; im < 4; im++) {
            int row = wm * 64 + im * 16 + (lane & 15);
            int slot = (lane >> 4);
            ldm_x4(afrag[0][im], Ab + row * 128 + (((uint32_t)(slot ^ (row & 7))) << 4));
        }
        #pragma unroll
        for (int jn = 0; jn < 2; jn++) {
            int grp = lane >> 3;
            int nrow = wn * 32 + jn * 16 + (grp >> 1) * 8 + (lane & 7);
            int slot = (grp & 1);
            ldm_x4(bfrag[0][jn], Bb + nrow * 128 + (((uint32_t)(slot ^ (nrow & 7))) << 4));
        }

        #pragma unroll
        for (int ks = 0; ks < 4; ks++) {
            const int cb = ks & 1;
            if (ks < 3) {
                const int nb = cb ^ 1;
                #pragma unroll
                for (int im = 0; im < 4; im++) {
                    int row = wm * 64 + im * 16 + (lane & 15);
                    int slot = (ks + 1) * 2 + (lane >> 4);
                    ldm_x4(afrag[nb][im], Ab + row * 128 + (((uint32_t)(slot ^ (row & 7))) << 4));
                }
                #pragma unroll
                for (int jn = 0; jn < 2; jn++) {
                    int grp = lane >> 3;
                    int nrow = wn * 32 + jn * 16 + (grp >> 1) * 8 + (lane & 7);
                    int slot = (ks + 1) * 2 + (grp & 1);
                    ldm_x4(bfrag[nb][jn], Bb + nrow * 128 + (((uint32_t)(slot ^ (nrow & 7))) << 4));
                }
            }
            #pragma unroll
            for (int im = 0; im < 4; im++)
                #pragma unroll
                for (int in = 0; in < 4; in++)
                    mma16816(acc[im][in], afrag[cb][im],
                             bfrag[cb][in >> 1][(in & 1) * 2 + 0],
                             bfrag[cb][in >> 1][(in & 1) * 2 + 1]);
        }

        // ---- finish next-stage fill ----
        if (more) {
            CP_WAIT0();
            if (!A_HALF) {
                #pragma unroll
                for (int j = 0; j < 8; j++) {
                    int idx = tid + j * 256;
                    int r = idx >> 4, g = idx & 15;
                    int s = g >> 1;
                    uint32_t off = stn + r * 128 + (((uint32_t)(s ^ (r & 7))) << 4) + (g & 1) * 8;
                    uint2 u;
                    u.x = pack_h2(areg[j].x, areg[j].y);
                    u.y = pack_h2(areg[j].z, areg[j].w);
                    *reinterpret_cast<uint2*>(smem + off) = u;
                }
            }
        }
        __syncthreads();
    }

    // ---- epilogue ----
    #pragma unroll
    for (int im = 0; im < 4; im++) {
        int r0 = m0 + wm * 64 + im * 16 + (lane >> 2);
        #pragma unroll
        for (int in = 0; in < 4; in++) {
            int col = n0 + wn * 32 + in * 8 + (lane & 3) * 2;
            if (FINAL) {
                float* D = (float*)Dptr;
                float b0 = bias[col], b1 = bias[col + 1];
                float2 v0 = make_float2(acc[im][in][0] + b0, acc[im][in][1] + b1);
                float2 v1 = make_float2(acc[im][in][2] + b0, acc[im][in][3] + b1);
                *reinterpret_cast<float2*>(D + (size_t)r0 * CDIM + col) = v0;
                *reinterpret_cast<float2*>(D + (size_t)(r0 + 8) * CDIM + col) = v1;
            } else {
                __half* D = (__half*)Dptr;
                *reinterpret_cast<uint32_t*>(D + (size_t)r0 * CDIM + col) =
                    pack_h2(acc[im][in][0], acc[im][in][1]);
                *reinterpret_cast<uint32_t*>(D + (size_t)(r0 + 8) * CDIM + col) =
                    pack_h2(acc[im][in][2], acc[im][in][3]);
            }
        }
    }
}

// ---------------- per-token 2-way attention ----------------
__global__ void __launch_bounds__(256) attn_kernel() {
    int gid = blockIdx.x * blockDim.x + threadIdx.x;   // 262144 = 32768 tokens * 8 heads
    int t = gid >> 3;
    int h = gid & 7;

    const __half* q  = g_q + (size_t)t * CDIM + h * HDIM;
    const __half* k0 = g_k + (size_t)(2 * t) * CDIM + h * HDIM;
    const __half* k1 = k0 + CDIM;
    const __half* v0 = g_v + (size_t)(2 * t) * CDIM + h * HDIM;
    const __half* v1 = v0 + CDIM;

    float l0 = 0.f, l1 = 0.f;
    #pragma unroll
    for (int i = 0; i < 12; i++) {                     // 12 * 8 halves = 96
        int4 qa = *reinterpret_cast<const int4*>(q + i * 8);
        int4 ka = *reinterpret_cast<const int4*>(k0 + i * 8);
        int4 kb = *reinterpret_cast<const int4*>(k1 + i * 8);
        const __half2* qh = reinterpret_cast<const __half2*>(&qa);
        const __half2* k0h = reinterpret_cast<const __half2*>(&ka);
        const __half2* k1h = reinterpret_cast<const __half2*>(&kb);
        #pragma unroll
        for (int j = 0; j < 4; j++) {
            float2 qf = __half22float2(qh[j]);
            float2 a = __half22float2(k0h[j]);
            float2 b = __half22float2(k1h[j]);
            l0 = fmaf(qf.x, a.x, l0); l0 = fmaf(qf.y, a.y, l0);
            l1 = fmaf(qf.x, b.x, l1); l1 = fmaf(qf.y, b.y, l1);
        }
    }
    const float scale = 0.1020620726159658f;           // 96^-0.5
    l0 *= scale; l1 *= scale;
    float m = fmaxf(l0, l1);
    float e0 = __expf(l0 - m), e1 = __expf(l1 - m);
    float inv = 1.f / (e0 + e1);
    float a0 = e0 * inv, a1 = e1 * inv;

    __half* x = g_x + (size_t)t * CDIM + h * HDIM;
    #pragma unroll
    for (int i = 0; i < 12; i++) {
        int4 va = *reinterpret_cast<const int4*>(v0 + i * 8);
        int4 vb = *reinterpret_cast<const int4*>(v1 + i * 8);
        const __half2* ah = reinterpret_cast<const __half2*>(&va);
        const __half2* bh = reinterpret_cast<const __half2*>(&vb);
        uint4 out;
        uint32_t* op = reinterpret_cast<uint32_t*>(&out);
        #pragma unroll
        for (int j = 0; j < 4; j++) {
            float2 fa = __half22float2(ah[j]);
            float2 fb = __half22float2(bh[j]);
            op[j] = pack_h2(a0 * fa.x + a1 * fb.x, a0 * fa.y + a1 * fb.y);
        }
        *reinterpret_cast<uint4*>(x + i * 8) = out;
    }
}

// ---------------- launch ----------------
extern "C" void kernel_launch(void* const* d_in, const int* in_sizes, int n_in,
                              void* d_out, int out_size) {
    const float* query = (const float*)d_in[0];
    const float* key   = (const float*)d_in[1];
    const float* value = (const float*)d_in[2];
    const float* Wq    = (const float*)d_in[3];
    const float* Wk    = (const float*)d_in[4];
    const float* Wp    = (const float*)d_in[5];
    const float* bp    = (const float*)d_in[6];

    cudaFuncSetAttribute(gemm_kernel<false, false>,
                         cudaFuncAttributeMaxDynamicSharedMemorySize, SMEM_BYTES);
    cudaFuncSetAttribute(gemm_kernel<true, true>,
                         cudaFuncAttributeMaxDynamicSharedMemorySize, SMEM_BYTES);

    __half *q, *k, *v, *x, *wq, *wk, *wp;
    cudaGetSymbolAddress((void**)&q,  g_q);
    cudaGetSymbolAddress((void**)&k,  g_k);
    cudaGetSymbolAddress((void**)&v,  g_v);
    cudaGetSymbolAddress((void**)&x,  g_x);
    cudaGetSymbolAddress((void**)&wq, g_wq);
    cudaGetSymbolAddress((void**)&wk, g_wk);
    cudaGetSymbolAddress((void**)&wp, g_wp);

    // 1) weights -> fp16
    convert_w_kernel<<<(3 * (CDIM * CDIM / 4) + 255) / 256, 256>>>(Wq, Wk, Wp);

    // 2-4) projections (note: reference applies Wk to BOTH key and value)
    // grid = (n-tiles, m-tiles): co-resident CTAs share the A panel via L2
    gemm_kernel<false, false><<<dim3(CDIM / BN, NTOK / BM), 256, SMEM_BYTES>>>(query, wq, nullptr, q);
    gemm_kernel<false, false><<<dim3(CDIM / BN, 2 * NTOK / BM), 256, SMEM_BYTES>>>(key, wk, nullptr, k);
    gemm_kernel<false, false><<<dim3(CDIM / BN, 2 * NTOK / BM), 256, SMEM_BYTES>>>(value, wk, nullptr, v);

    // 5) per-token 2-way softmax attention
    attn_kernel<<<(NTOK * 8) / 256, 256>>>();

    // 6) output projection + bias (fp32 out)
    gemm_kernel<true, true><<<dim3(CDIM / BN, NTOK / BM), 256, SMEM_BYTES>>>(x, wp, bp, (float*)d_out);
}